// round 7
// baseline (speedup 1.0000x reference)
#include <cuda_runtime.h>
#include <math.h>

// Problem constants (fixed by setup_inputs)
#define NVOX   (64*64*64)
#define BATCH  2
#define NPART  32768
#define CIN    4
#define CMID   32
#define COUTC  4

// Scratch buffers (device globals: no allocation allowed)
__device__ float g_grid0[BATCH*CIN *NVOX];   // splat output [B,4,64,64,64] NCDHW
__device__ float g_bufA [BATCH*CMID*NVOX];   // [B,32,...]
__device__ float g_bufB [BATCH*CMID*NVOX];   // [B,32,...]
__device__ float g_out4 [BATCH*COUTC*NVOX];  // final conv output [B,4,...]

__device__ __forceinline__ float* buf_ptr(int s) {
    switch (s) {
        case 0: return g_grid0;
        case 1: return g_bufA;
        case 2: return g_bufB;
        default: return g_out4;
    }
}

// ---- packed fp32x2 helpers (Blackwell packed datapath, PTX-only) ----------
__device__ __forceinline__ unsigned long long bcast2(float v) {
    unsigned long long r;
    unsigned int b = __float_as_uint(v);
    asm("mov.b64 %0, {%1, %1};" : "=l"(r) : "r"(b));
    return r;
}
__device__ __forceinline__ void ffma2(unsigned long long& acc,
                                      unsigned long long a,
                                      unsigned long long b) {
    asm("fma.rn.f32x2 %0, %1, %2, %0;" : "+l"(acc) : "l"(a), "l"(b));
}
__device__ __forceinline__ void unpack2(unsigned long long v, float& lo, float& hi) {
    unsigned int l, h;
    asm("mov.b64 {%0, %1}, %2;" : "=r"(l), "=r"(h) : "l"(v));
    lo = __uint_as_float(l);
    hi = __uint_as_float(h);
}

// ---------------------------------------------------------------------------
// Zero the splat accumulator grid
// ---------------------------------------------------------------------------
__global__ void zero_grid0_kernel() {
    int n = BATCH * CIN * NVOX;
    for (int i = blockIdx.x * blockDim.x + threadIdx.x; i < n;
         i += gridDim.x * blockDim.x)
        g_grid0[i] = 0.0f;
}

// ---------------------------------------------------------------------------
// particles2grid: SPH poly6 splat with scattered atomics
// ---------------------------------------------------------------------------
__global__ void splat_kernel(const float* __restrict__ locs,
                             const float* __restrict__ data,
                             const float* __restrict__ dens) {
    int p = blockIdx.x * blockDim.x + threadIdx.x;
    if (p >= BATCH * NPART) return;
    int b = p / NPART;

    float lx = locs[3*p+0], ly = locs[3*p+1], lz = locs[3*p+2];
    float inv = 1.0f / dens[p];
    float d0 = data[4*p+0]*inv, d1 = data[4*p+1]*inv;
    float d2c = data[4*p+2]*inv, d3 = data[4*p+3]*inv;

    const float STEP = 0.015625f;       // 1/64
    const float INVSTEP = 64.0f;
    const float H2 = 0.0009765625f;     // h^2, h = 0.03125
    const float C6 = (float)(315.0 / (64.0 * 3.14159265358979323846 *
                                       2.8421709430404007e-14));

    int bx = (int)floorf(lx * INVSTEP);
    int by = (int)floorf(ly * INVSTEP);
    int bz = (int)floorf(lz * INVSTEP);

    float* gb = g_grid0 + (size_t)b * CIN * NVOX;

    for (int ox = -2; ox <= 2; ++ox) {
        int cx = bx + ox;
        if ((unsigned)cx >= 64u) continue;
        float ddx = ((float)cx + 0.5f) * STEP - lx;
        float sx = ddx * ddx;
        for (int oy = -2; oy <= 2; ++oy) {
            int cy = by + oy;
            if ((unsigned)cy >= 64u) continue;
            float ddy = ((float)cy + 0.5f) * STEP - ly;
            float sxy = sx + ddy * ddy;
            if (sxy > H2) continue;
            for (int oz = -2; oz <= 2; ++oz) {
                int cz = bz + oz;
                if ((unsigned)cz >= 64u) continue;
                float ddz = ((float)cz + 0.5f) * STEP - lz;
                float dd2 = sxy + ddz * ddz;
                if (dd2 > H2) continue;
                float t = H2 - dd2;
                float w = C6 * t * t * t;
                int flat = ((cx << 6) + cy) * 64 + cz;
                atomicAdd(gb + 0*NVOX + flat, w * d0);
                atomicAdd(gb + 1*NVOX + flat, w * d1);
                atomicAdd(gb + 2*NVOX + flat, w * d2c);
                atomicAdd(gb + 3*NVOX + flat, w * d3);
            }
        }
    }
}

// ---------------------------------------------------------------------------
// Direct 3x3x3 conv (NCDHW, SAME, cross-correlation) + optional PReLU.
// Block = 8x8x8 output tile. Threads = 64 * (CO/CO_PER): (x:8, y:8, cog).
// Each thread computes ALL 8 z voxels x CO_PER output channels:
//   32 packed f32x2 accumulators (co-pairs), weight pairs via broadcast
//   LDS.64 from s_w[tap][co], values broadcast-packed once per (dx,dy).
// Aux:FFMA2 instruction ratio ~0.28 -> fma-pipe-bound.
// ---------------------------------------------------------------------------
template <int CI, int CO, int CO_PER, bool PRELU>
__global__ void __launch_bounds__(64 * (CO / CO_PER))
conv3d_kernel(int in_sel, int out_sel,
              const float* __restrict__ W,
              const float* __restrict__ bias,
              const float* __restrict__ alpha) {
    constexpr int NP = CO_PER / 2;           // packed accumulator pairs
    constexpr int NT = 64 * (CO / CO_PER);   // threads per block
    const float* in  = buf_ptr(in_sel);
    float*       out = buf_ptr(out_sel);

    int tid = threadIdx.x;
    int x   = tid & 7;
    int y   = (tid >> 3) & 7;
    int cog = tid >> 6;

    int bidx = blockIdx.x;
    int tz = bidx & 7, ty = (bidx >> 3) & 7, tx = (bidx >> 6) & 7;
    int b  = bidx >> 9;
    int ox = tx << 3, oy = ty << 3, oz = tz << 3;

    __shared__ __align__(16) float s_tile[1000];   // 10x10x10 input tile (one ci)
    __shared__ __align__(16) float s_w[27 * CO];   // weights, layout [tap][co]

    unsigned long long acc2[8][NP];
#pragma unroll
    for (int t = 0; t < 8; ++t)
#pragma unroll
        for (int j = 0; j < NP; ++j) acc2[t][j] = 0ULL;

    const float* inb = in + (size_t)b * CI * NVOX;
    const int cobase = cog * CO_PER;

    for (int ci = 0; ci < CI; ++ci) {
        const float* inc = inb + ci * NVOX;
        // load 10^3 input tile (halo=1), zero-padded at volume boundary
        for (int i = tid; i < 1000; i += NT) {
            int lz = i % 10; int r = i / 10; int ly = r % 10; int lx = r / 10;
            int gx = ox + lx - 1, gy = oy + ly - 1, gz = oz + lz - 1;
            float v = 0.0f;
            if ((unsigned)gx < 64u && (unsigned)gy < 64u && (unsigned)gz < 64u)
                v = __ldg(inc + (((gx << 6) + gy) << 6) + gz);
            s_tile[i] = v;
        }
        // stage weights for this ci as s_w[tap*CO + co] (co contiguous)
        for (int i = tid; i < CO * 27; i += NT) {
            int co = i % CO; int tap = i / CO;
            s_w[i] = W[co * (CI * 27) + ci * 27 + tap];
        }
        __syncthreads();

#pragma unroll
        for (int dx = 0; dx < 3; ++dx) {
#pragma unroll
            for (int dy = 0; dy < 3; ++dy) {
                const float* tp = s_tile + ((x + dx) * 10 + (y + dy)) * 10;
                // 10 consecutive z values, 8B-aligned (even offsets)
                unsigned long long vb[10];
#pragma unroll
                for (int k = 0; k < 5; ++k) {
                    float2 p = *reinterpret_cast<const float2*>(tp + 2 * k);
                    vb[2 * k]     = bcast2(p.x);
                    vb[2 * k + 1] = bcast2(p.y);
                }
#pragma unroll
                for (int dz = 0; dz < 3; ++dz) {
                    int tap = (dx * 3 + dy) * 3 + dz;
                    const unsigned long long* wp =
                        reinterpret_cast<const unsigned long long*>(
                            s_w + tap * CO + cobase);
                    unsigned long long wr[NP];
#pragma unroll
                    for (int j = 0; j < NP; ++j) wr[j] = wp[j];   // LDS.64 bcast
#pragma unroll
                    for (int t = 0; t < 8; ++t)
#pragma unroll
                        for (int j = 0; j < NP; ++j)
                            ffma2(acc2[t][j], vb[t + dz], wr[j]);
                }
            }
        }
        __syncthreads();
    }

    float a = 0.0f;
    if (PRELU) a = alpha[0];
#pragma unroll
    for (int j = 0; j < NP; ++j) {
        int co0 = cobase + 2 * j;
        float bb0 = bias[co0], bb1 = bias[co0 + 1];
        float r0[8], r1[8];
#pragma unroll
        for (int t = 0; t < 8; ++t) {
            float lo, hi;
            unpack2(acc2[t][j], lo, hi);
            lo += bb0; hi += bb1;
            if (PRELU) {
                lo = (lo >= 0.0f) ? lo : a * lo;
                hi = (hi >= 0.0f) ? hi : a * hi;
            }
            r0[t] = lo; r1[t] = hi;
        }
        size_t spatial = ((((size_t)(ox + x) << 6) + (oy + y)) << 6) + oz;
        size_t o0 = (size_t)(b * CO + co0) * NVOX + spatial;
        *reinterpret_cast<float4*>(out + o0) =
            make_float4(r0[0], r0[1], r0[2], r0[3]);
        *reinterpret_cast<float4*>(out + o0 + 4) =
            make_float4(r0[4], r0[5], r0[6], r0[7]);
        *reinterpret_cast<float4*>(out + o0 + NVOX) =
            make_float4(r1[0], r1[1], r1[2], r1[3]);
        *reinterpret_cast<float4*>(out + o0 + NVOX + 4) =
            make_float4(r1[4], r1[5], r1[6], r1[7]);
    }
}

// ---------------------------------------------------------------------------
// grid2particles: trilinear gather of g_out4 at particle locations
// ---------------------------------------------------------------------------
__global__ void gather_kernel(const float* __restrict__ locs,
                              float* __restrict__ out) {
    int p = blockIdx.x * blockDim.x + threadIdx.x;
    if (p >= BATCH * NPART) return;
    int b = p / NPART;
    const float* g = g_out4 + (size_t)b * COUTC * NVOX;

    float px = locs[3*p+0] * 64.0f - 0.5f;
    float py = locs[3*p+1] * 64.0f - 0.5f;
    float pz = locs[3*p+2] * 64.0f - 0.5f;
    int ix = (int)floorf(px), iy = (int)floorf(py), iz = (int)floorf(pz);
    float fx = px - (float)ix, fy = py - (float)iy, fz = pz - (float)iz;

    float r0 = 0.f, r1 = 0.f, r2 = 0.f, r3 = 0.f;
#pragma unroll
    for (int dx = 0; dx < 2; ++dx) {
        int jx = ix + dx;
        float wx = dx ? fx : 1.0f - fx;
#pragma unroll
        for (int dy = 0; dy < 2; ++dy) {
            int jy = iy + dy;
            float wxy = wx * (dy ? fy : 1.0f - fy);
#pragma unroll
            for (int dz = 0; dz < 2; ++dz) {
                int jz = iz + dz;
                float w = wxy * (dz ? fz : 1.0f - fz);
                if ((unsigned)jx < 64u && (unsigned)jy < 64u && (unsigned)jz < 64u) {
                    int flat = ((jx << 6) + jy) * 64 + jz;
                    r0 += w * g[0*NVOX + flat];
                    r1 += w * g[1*NVOX + flat];
                    r2 += w * g[2*NVOX + flat];
                    r3 += w * g[3*NVOX + flat];
                }
            }
        }
    }
    out[4*p+0] = r0;
    out[4*p+1] = r1;
    out[4*p+2] = r2;
    out[4*p+3] = r3;
}

// ---------------------------------------------------------------------------
// kernel_launch
// ---------------------------------------------------------------------------
extern "C" void kernel_launch(void* const* d_in, const int* in_sizes, int n_in,
                              void* d_out, int out_size) {
    const float* locs = (const float*)d_in[0];
    const float* data = (const float*)d_in[1];
    const float* dens = (const float*)d_in[2];
    const float* W0 = (const float*)d_in[3];
    const float* b0 = (const float*)d_in[4];
    const float* W1 = (const float*)d_in[5];
    const float* b1 = (const float*)d_in[6];
    const float* W2 = (const float*)d_in[7];
    const float* b2 = (const float*)d_in[8];
    const float* W3 = (const float*)d_in[9];
    const float* b3 = (const float*)d_in[10];
    const float* a0 = (const float*)d_in[11];
    const float* a1 = (const float*)d_in[12];
    const float* a2 = (const float*)d_in[13];
    float* out = (float*)d_out;

    (void)in_sizes; (void)n_in; (void)out_size;

    // 1. zero splat grid
    zero_grid0_kernel<<<512, 256>>>();

    // 2. particles -> grid (SPH poly6 splat)
    splat_kernel<<<(BATCH * NPART + 127) / 128, 128>>>(locs, data, dens);

    // 3. conv stack (NCDHW). 8^3 tiles, 512 tiles * B = 1024 blocks
    conv3d_kernel<CIN,  CMID,  8, true ><<<1024, 256>>>(0, 1, W0, b0, a0);
    conv3d_kernel<CMID, CMID,  8, true ><<<1024, 256>>>(1, 2, W1, b1, a1);
    conv3d_kernel<CMID, CMID,  8, true ><<<1024, 256>>>(2, 1, W2, b2, a2);
    conv3d_kernel<CMID, COUTC, 2, false><<<1024, 128>>>(1, 3, W3, b3, a0);

    // 4. grid -> particles (trilinear)
    gather_kernel<<<(BATCH * NPART + 127) / 128, 128>>>(locs, out);
}

// round 8
// speedup vs baseline: 1.1760x; 1.1760x over previous
#include <cuda_runtime.h>
#include <math.h>

// Problem constants (fixed by setup_inputs)
#define NVOX   (64*64*64)
#define BATCH  2
#define NPART  32768
#define CIN    4
#define CMID   32
#define COUTC  4

// Scratch buffers (device globals: no allocation allowed)
__device__ float g_grid0[BATCH*CIN *NVOX];   // splat output [B,4,64,64,64] NCDHW
__device__ float g_bufA [BATCH*CMID*NVOX];   // [B,32,...]
__device__ float g_bufB [BATCH*CMID*NVOX];   // [B,32,...]
__device__ float g_out4 [BATCH*COUTC*NVOX];  // final conv output [B,4,...]

__device__ __forceinline__ float* buf_ptr(int s) {
    switch (s) {
        case 0: return g_grid0;
        case 1: return g_bufA;
        case 2: return g_bufB;
        default: return g_out4;
    }
}

// ---- packed fp32x2 helpers (Blackwell packed datapath, PTX-only) ----------
__device__ __forceinline__ unsigned long long bcast2(float v) {
    unsigned long long r;
    unsigned int b = __float_as_uint(v);
    asm("mov.b64 %0, {%1, %1};" : "=l"(r) : "r"(b));
    return r;
}
__device__ __forceinline__ void ffma2(unsigned long long& acc,
                                      unsigned long long a,
                                      unsigned long long b) {
    asm("fma.rn.f32x2 %0, %1, %2, %0;" : "+l"(acc) : "l"(a), "l"(b));
}
__device__ __forceinline__ void unpack2(unsigned long long v, float& lo, float& hi) {
    unsigned int l, h;
    asm("mov.b64 {%0, %1}, %2;" : "=r"(l), "=r"(h) : "l"(v));
    lo = __uint_as_float(l);
    hi = __uint_as_float(h);
}

// ---------------------------------------------------------------------------
// Zero the splat accumulator grid
// ---------------------------------------------------------------------------
__global__ void zero_grid0_kernel() {
    int n = BATCH * CIN * NVOX;
    for (int i = blockIdx.x * blockDim.x + threadIdx.x; i < n;
         i += gridDim.x * blockDim.x)
        g_grid0[i] = 0.0f;
}

// ---------------------------------------------------------------------------
// particles2grid: SPH poly6 splat with scattered atomics
// ---------------------------------------------------------------------------
__global__ void splat_kernel(const float* __restrict__ locs,
                             const float* __restrict__ data,
                             const float* __restrict__ dens) {
    int p = blockIdx.x * blockDim.x + threadIdx.x;
    if (p >= BATCH * NPART) return;
    int b = p / NPART;

    float lx = locs[3*p+0], ly = locs[3*p+1], lz = locs[3*p+2];
    float inv = 1.0f / dens[p];
    float d0 = data[4*p+0]*inv, d1 = data[4*p+1]*inv;
    float d2c = data[4*p+2]*inv, d3 = data[4*p+3]*inv;

    const float STEP = 0.015625f;       // 1/64
    const float INVSTEP = 64.0f;
    const float H2 = 0.0009765625f;     // h^2, h = 0.03125
    const float C6 = (float)(315.0 / (64.0 * 3.14159265358979323846 *
                                       2.8421709430404007e-14));

    int bx = (int)floorf(lx * INVSTEP);
    int by = (int)floorf(ly * INVSTEP);
    int bz = (int)floorf(lz * INVSTEP);

    float* gb = g_grid0 + (size_t)b * CIN * NVOX;

    for (int ox = -2; ox <= 2; ++ox) {
        int cx = bx + ox;
        if ((unsigned)cx >= 64u) continue;
        float ddx = ((float)cx + 0.5f) * STEP - lx;
        float sx = ddx * ddx;
        for (int oy = -2; oy <= 2; ++oy) {
            int cy = by + oy;
            if ((unsigned)cy >= 64u) continue;
            float ddy = ((float)cy + 0.5f) * STEP - ly;
            float sxy = sx + ddy * ddy;
            if (sxy > H2) continue;
            for (int oz = -2; oz <= 2; ++oz) {
                int cz = bz + oz;
                if ((unsigned)cz >= 64u) continue;
                float ddz = ((float)cz + 0.5f) * STEP - lz;
                float dd2 = sxy + ddz * ddz;
                if (dd2 > H2) continue;
                float t = H2 - dd2;
                float w = C6 * t * t * t;
                int flat = ((cx << 6) + cy) * 64 + cz;
                atomicAdd(gb + 0*NVOX + flat, w * d0);
                atomicAdd(gb + 1*NVOX + flat, w * d1);
                atomicAdd(gb + 2*NVOX + flat, w * d2c);
                atomicAdd(gb + 3*NVOX + flat, w * d3);
            }
        }
    }
}

// ---------------------------------------------------------------------------
// Direct 3x3x3 conv (NCDHW, SAME, cross-correlation) + optional PReLU.
// Block = 8x8x8 output tile. Threads = 128*(CO/CO_PER): (x:8,y:8,zg:2,cog).
// Each thread: 4 consecutive z voxels x CO_PER output channels as packed
// f32x2 co-pair accumulators (fma.rn.f32x2, weight pairs via LDS.64).
//
// Overhead removal vs naive per-ci loop:
//  - tile gmem offsets precomputed ONCE per block (sentinel -1 = halo)
//  - weights staged in 16-ci chunks (2 stagings/block instead of 32)
//  - double-buffered tile -> 1 barrier per ci
//  - tile(ci+1) LDG prefetch overlapped with compute(ci)
// ---------------------------------------------------------------------------
template <int CI, int CO, int CO_PER, bool PRELU>
__global__ void __launch_bounds__(128 * (CO / CO_PER), 2)
conv3d_kernel(int in_sel, int out_sel,
              const float* __restrict__ W,
              const float* __restrict__ bias,
              const float* __restrict__ alpha) {
    constexpr int NP     = CO_PER / 2;            // packed accumulator pairs
    constexpr int NT     = 128 * (CO / CO_PER);   // threads per block
    constexpr int WCHUNK = (CI < 16) ? CI : 16;   // ci per weight chunk
    constexpr int WELEMS = WCHUNK * 27 * CO;
    constexpr int NLOAD  = (1000 + NT - 1) / NT;  // tile loads per thread

    const float* in  = buf_ptr(in_sel);
    float*       out = buf_ptr(out_sel);

    int tid = threadIdx.x;
    int x   = tid & 7;
    int y   = (tid >> 3) & 7;
    int zg  = (tid >> 6) & 1;
    int cog = tid >> 7;

    int bidx = blockIdx.x;
    int tz = bidx & 7, ty = (bidx >> 3) & 7, tx = (bidx >> 6) & 7;
    int b  = bidx >> 9;
    int ox = tx << 3, oy = ty << 3, oz = tz << 3;
    int z0 = zg << 2;

    __shared__ __align__(16) float s_tile[2][1000];  // double-buffered 10^3 tile
    __shared__ __align__(16) float s_w[WELEMS];      // weights [c][tap][co]

    // ---- precompute tile-load gmem offsets (once per block) ----
    int offs[NLOAD];
#pragma unroll
    for (int k = 0; k < NLOAD; ++k) {
        int i = tid + k * NT;
        offs[k] = -1;
        if (i < 1000) {
            int lz = i % 10; int r = i / 10; int ly = r % 10; int lx = r / 10;
            int gx = ox + lx - 1, gy = oy + ly - 1, gz = oz + lz - 1;
            if ((unsigned)gx < 64u && (unsigned)gy < 64u && (unsigned)gz < 64u)
                offs[k] = (((gx << 6) + gy) << 6) + gz;
        }
    }

    unsigned long long acc2[4][NP];
#pragma unroll
    for (int t = 0; t < 4; ++t)
#pragma unroll
        for (int j = 0; j < NP; ++j) acc2[t][j] = 0ULL;

    const float* inb = in + (size_t)b * CI * NVOX;
    const int cobase = cog * CO_PER;

    // ---- prologue: fetch tile(0) and store into buffer 0 ----
    float pv[NLOAD];
#pragma unroll
    for (int k = 0; k < NLOAD; ++k)
        pv[k] = (offs[k] >= 0) ? __ldg(inb + offs[k]) : 0.0f;
#pragma unroll
    for (int k = 0; k < NLOAD; ++k) {
        int i = tid + k * NT;
        if (i < 1000) s_tile[0][i] = pv[k];
    }

    int cur = 0;
    for (int ci = 0; ci < CI; ++ci) {
        int c = ci % WCHUNK;
        if (c == 0) {
            if (ci > 0) __syncthreads();   // drain readers of old s_w
            // stage weights for this chunk: s_w[(c*27+tap)*CO+co]
            int chunk = ci / WCHUNK;
            for (int i = tid; i < WELEMS; i += NT) {
                int co = i % CO; int t2 = i / CO;
                int tap = t2 % 27; int cc = t2 / 27;
                s_w[i] = W[co * (CI * 27) + (chunk * WCHUNK + cc) * 27 + tap];
            }
        }
        __syncthreads();   // tile STS (+ weights) visible

        // prefetch tile(ci+1) — LDG latency hides under compute below
        if (ci + 1 < CI) {
            const float* incn = inb + (ci + 1) * NVOX;
#pragma unroll
            for (int k = 0; k < NLOAD; ++k)
                pv[k] = (offs[k] >= 0) ? __ldg(incn + offs[k]) : 0.0f;
        }

        const float* tile = s_tile[cur];
        const float* swc  = s_w + c * 27 * CO;
#pragma unroll
        for (int dx = 0; dx < 3; ++dx) {
#pragma unroll
            for (int dy = 0; dy < 3; ++dy) {
                const float* tp = tile + ((x + dx) * 10 + (y + dy)) * 10 + z0;
                float2 p0 = *reinterpret_cast<const float2*>(tp + 0);
                float2 p1 = *reinterpret_cast<const float2*>(tp + 2);
                float2 p2 = *reinterpret_cast<const float2*>(tp + 4);
                unsigned long long vb[6];
                vb[0] = bcast2(p0.x); vb[1] = bcast2(p0.y);
                vb[2] = bcast2(p1.x); vb[3] = bcast2(p1.y);
                vb[4] = bcast2(p2.x); vb[5] = bcast2(p2.y);
#pragma unroll
                for (int dz = 0; dz < 3; ++dz) {
                    int tap = (dx * 3 + dy) * 3 + dz;
                    const unsigned long long* wp =
                        reinterpret_cast<const unsigned long long*>(
                            swc + tap * CO + cobase);
                    unsigned long long wr[NP];
#pragma unroll
                    for (int j = 0; j < NP; ++j) wr[j] = wp[j];   // LDS.64
#pragma unroll
                    for (int t = 0; t < 4; ++t)
#pragma unroll
                        for (int j = 0; j < NP; ++j)
                            ffma2(acc2[t][j], vb[t + dz], wr[j]);
                }
            }
        }

        // store prefetched tile into the other buffer
        if (ci + 1 < CI) {
#pragma unroll
            for (int k = 0; k < NLOAD; ++k) {
                int i = tid + k * NT;
                if (i < 1000) s_tile[cur ^ 1][i] = pv[k];
            }
            cur ^= 1;
        }
    }

    float a = 0.0f;
    if (PRELU) a = alpha[0];
#pragma unroll
    for (int j = 0; j < NP; ++j) {
        int co0 = cobase + 2 * j;
        float bb0 = bias[co0], bb1 = bias[co0 + 1];
        float r0[4], r1[4];
#pragma unroll
        for (int t = 0; t < 4; ++t) {
            float lo, hi;
            unpack2(acc2[t][j], lo, hi);
            lo += bb0; hi += bb1;
            if (PRELU) {
                lo = (lo >= 0.0f) ? lo : a * lo;
                hi = (hi >= 0.0f) ? hi : a * hi;
            }
            r0[t] = lo; r1[t] = hi;
        }
        size_t spatial = ((((size_t)(ox + x) << 6) + (oy + y)) << 6) + oz + z0;
        size_t o0 = (size_t)(b * CO + co0) * NVOX + spatial;
        *reinterpret_cast<float4*>(out + o0) =
            make_float4(r0[0], r0[1], r0[2], r0[3]);
        *reinterpret_cast<float4*>(out + o0 + NVOX) =
            make_float4(r1[0], r1[1], r1[2], r1[3]);
    }
}

// ---------------------------------------------------------------------------
// grid2particles: trilinear gather of g_out4 at particle locations
// ---------------------------------------------------------------------------
__global__ void gather_kernel(const float* __restrict__ locs,
                              float* __restrict__ out) {
    int p = blockIdx.x * blockDim.x + threadIdx.x;
    if (p >= BATCH * NPART) return;
    int b = p / NPART;
    const float* g = g_out4 + (size_t)b * COUTC * NVOX;

    float px = locs[3*p+0] * 64.0f - 0.5f;
    float py = locs[3*p+1] * 64.0f - 0.5f;
    float pz = locs[3*p+2] * 64.0f - 0.5f;
    int ix = (int)floorf(px), iy = (int)floorf(py), iz = (int)floorf(pz);
    float fx = px - (float)ix, fy = py - (float)iy, fz = pz - (float)iz;

    float r0 = 0.f, r1 = 0.f, r2 = 0.f, r3 = 0.f;
#pragma unroll
    for (int dx = 0; dx < 2; ++dx) {
        int jx = ix + dx;
        float wx = dx ? fx : 1.0f - fx;
#pragma unroll
        for (int dy = 0; dy < 2; ++dy) {
            int jy = iy + dy;
            float wxy = wx * (dy ? fy : 1.0f - fy);
#pragma unroll
            for (int dz = 0; dz < 2; ++dz) {
                int jz = iz + dz;
                float w = wxy * (dz ? fz : 1.0f - fz);
                if ((unsigned)jx < 64u && (unsigned)jy < 64u && (unsigned)jz < 64u) {
                    int flat = ((jx << 6) + jy) * 64 + jz;
                    r0 += w * g[0*NVOX + flat];
                    r1 += w * g[1*NVOX + flat];
                    r2 += w * g[2*NVOX + flat];
                    r3 += w * g[3*NVOX + flat];
                }
            }
        }
    }
    out[4*p+0] = r0;
    out[4*p+1] = r1;
    out[4*p+2] = r2;
    out[4*p+3] = r3;
}

// ---------------------------------------------------------------------------
// kernel_launch
// ---------------------------------------------------------------------------
extern "C" void kernel_launch(void* const* d_in, const int* in_sizes, int n_in,
                              void* d_out, int out_size) {
    const float* locs = (const float*)d_in[0];
    const float* data = (const float*)d_in[1];
    const float* dens = (const float*)d_in[2];
    const float* W0 = (const float*)d_in[3];
    const float* b0 = (const float*)d_in[4];
    const float* W1 = (const float*)d_in[5];
    const float* b1 = (const float*)d_in[6];
    const float* W2 = (const float*)d_in[7];
    const float* b2 = (const float*)d_in[8];
    const float* W3 = (const float*)d_in[9];
    const float* b3 = (const float*)d_in[10];
    const float* a0 = (const float*)d_in[11];
    const float* a1 = (const float*)d_in[12];
    const float* a2 = (const float*)d_in[13];
    float* out = (float*)d_out;

    (void)in_sizes; (void)n_in; (void)out_size;

    // 1. zero splat grid
    zero_grid0_kernel<<<512, 256>>>();

    // 2. particles -> grid (SPH poly6 splat)
    splat_kernel<<<(BATCH * NPART + 127) / 128, 128>>>(locs, data, dens);

    // 3. conv stack (NCDHW). 8^3 tiles, 512 tiles * B = 1024 blocks
    conv3d_kernel<CIN,  CMID,  8, true ><<<1024, 512>>>(0, 1, W0, b0, a0);
    conv3d_kernel<CMID, CMID,  8, true ><<<1024, 512>>>(1, 2, W1, b1, a1);
    conv3d_kernel<CMID, CMID,  8, true ><<<1024, 512>>>(2, 1, W2, b2, a2);
    conv3d_kernel<CMID, COUTC, 2, false><<<1024, 256>>>(1, 3, W3, b3, a0);

    // 4. grid -> particles (trilinear)
    gather_kernel<<<(BATCH * NPART + 127) / 128, 128>>>(locs, out);
}